// round 4
// baseline (speedup 1.0000x reference)
#include <cuda_runtime.h>

#define NHID 20
#define TPB  256
#define PPT  2   // points per thread = 1 f32x2 pair

typedef unsigned long long u64;

static __device__ __forceinline__ u64 pack2f(float lo, float hi) {
    u64 r;
    unsigned a = __float_as_uint(lo), b = __float_as_uint(hi);
    asm("mov.b64 %0, {%1, %2};" : "=l"(r) : "r"(a), "r"(b));
    return r;
}
static __device__ __forceinline__ void unpack2f(u64 v, float& lo, float& hi) {
    unsigned a, b;
    asm("mov.b64 {%0, %1}, %2;" : "=r"(a), "=r"(b) : "l"(v));
    lo = __uint_as_float(a);
    hi = __uint_as_float(b);
}
static __device__ __forceinline__ u64 fma2(u64 a, u64 b, u64 c) {
    u64 d;
    asm("fma.rn.f32x2 %0, %1, %2, %3;" : "=l"(d) : "l"(a), "l"(b), "l"(c));
    return d;
}
static __device__ __forceinline__ u64 mul2(u64 a, u64 b) {
    u64 d;
    asm("mul.rn.f32x2 %0, %1, %2;" : "=l"(d) : "l"(a), "l"(b));
    return d;
}
static __device__ __forceinline__ u64 add2(u64 a, u64 b) {
    u64 d;
    asm("add.rn.f32x2 %0, %1, %2;" : "=l"(d) : "l"(a), "l"(b));
    return d;
}
static __device__ __forceinline__ float ex2f(float x) {
    float r;
    asm("ex2.approx.f32 %0, %1;" : "=f"(r) : "f"(x));
    return r;
}
static __device__ __forceinline__ float rcpf(float x) {
    float r;
    asm("rcp.approx.f32 %0, %1;" : "=f"(r) : "f"(x));
    return r;
}

// silu on a packed pair: x * 1/(1+e^-x).  3 f32x2 fma-pipe ops + 4 MUFU.
static __device__ __forceinline__ u64 silu2(u64 x2, u64 negl2e2, u64 one2) {
    u64 m = mul2(x2, negl2e2);              // -x*log2(e)
    float mlo, mhi; unpack2f(m, mlo, mhi);
    u64 e = pack2f(ex2f(mlo), ex2f(mhi));   // e^-x
    u64 d = add2(e, one2);                  // 1 + e^-x
    float dlo, dhi; unpack2f(d, dlo, dhi);
    u64 r = pack2f(rcpf(dlo), rcpf(dhi));   // sigmoid
    return mul2(x2, r);
}

// One 20->20 hidden layer: src -> dst (distinct buffers).
// LDS.128 fetches two weight splat-pairs per instruction; even/odd dual
// accumulator chains break the serial FMA dependency.
static __device__ __forceinline__ void layer20(
    const u64* __restrict__ wl, const u64* __restrict__ bl,
    const u64* __restrict__ src, u64* __restrict__ dst,
    u64 NEGL2E2, u64 ONE2, u64 ZERO2)
{
    #pragma unroll
    for (int j = 0; j < NHID; j++) {
        const ulonglong2* wrow = reinterpret_cast<const ulonglong2*>(wl + j * NHID);
        u64 accE = bl[j];
        u64 accO = ZERO2;
        #pragma unroll
        for (int k2 = 0; k2 < NHID / 2; k2++) {
            ulonglong2 w = wrow[k2];             // LDS.128 broadcast
            accE = fma2(src[2 * k2],     w.x, accE);
            accO = fma2(src[2 * k2 + 1], w.y, accO);
        }
        dst[j] = silu2(add2(accE, accO), NEGL2E2, ONE2);
    }
}

__global__ void __launch_bounds__(TPB, 2)   // cap regs at 128 -> 4 warps/SMSP
SpringEquationNN_kernel(
    const float* __restrict__ t,
    const float* __restrict__ W0, const float* __restrict__ b0,
    const float* __restrict__ W1, const float* __restrict__ b1,
    const float* __restrict__ W2, const float* __restrict__ b2,
    const float* __restrict__ W3, const float* __restrict__ b3,
    const float* __restrict__ W4, const float* __restrict__ b4,
    const float* __restrict__ W5, const float* __restrict__ b5,
    const float* __restrict__ W6, const float* __restrict__ b6,
    const float* __restrict__ W7, const float* __restrict__ b7,
    float* __restrict__ out, int n)
{
    // Weights duplicated as {w,w} pairs, 16B-aligned rows (NHID even).
    __shared__ __align__(16) u64 sW[6 * NHID * NHID];
    __shared__ __align__(16) u64 sB[6 * NHID];
    __shared__ __align__(16) u64 sW0[NHID], sB0[NHID], sW7[NHID];
    __shared__ float sb7;

    const int tid = threadIdx.x;

    for (int i = tid; i < NHID; i += TPB) {
        sW0[i] = pack2f(W0[i], W0[i]);
        sB0[i] = pack2f(b0[i], b0[i]);
        sW7[i] = pack2f(W7[i], W7[i]);
    }
    for (int i = tid; i < 6 * NHID * NHID; i += TPB) {
        int l = i / (NHID * NHID);
        int r = i - l * (NHID * NHID);
        float w;
        switch (l) {
            case 0: w = W1[r]; break;
            case 1: w = W2[r]; break;
            case 2: w = W3[r]; break;
            case 3: w = W4[r]; break;
            case 4: w = W5[r]; break;
            default: w = W6[r]; break;
        }
        sW[i] = pack2f(w, w);
    }
    for (int i = tid; i < 6 * NHID; i += TPB) {
        int l = i / NHID;
        int r = i - l * NHID;
        float w;
        switch (l) {
            case 0: w = b1[r]; break;
            case 1: w = b2[r]; break;
            case 2: w = b3[r]; break;
            case 3: w = b4[r]; break;
            case 4: w = b5[r]; break;
            default: w = b6[r]; break;
        }
        sB[i] = pack2f(w, w);
    }
    if (tid == 0) sb7 = b7[0];
    __syncthreads();

    const u64 NEGL2E2 = pack2f(-1.442695041f, -1.442695041f);
    const u64 ONE2    = pack2f(1.0f, 1.0f);
    const u64 ZERO2   = 0ull;

    const int base = (blockIdx.x * TPB + tid) * PPT;
    if (base >= n) return;

    float tx = t[base];
    float ty = (base + 1 < n) ? t[base + 1] : 0.0f;
    const u64 x0 = pack2f(tx, ty);

    u64 h[NHID], hn[NHID];

    // Layer 0: 1 -> 20
    #pragma unroll
    for (int j = 0; j < NHID; j++)
        h[j] = silu2(fma2(x0, sW0[j], sB0[j]), NEGL2E2, ONE2);

    // Hidden layers 1..6: ping-pong h <-> hn (no copy-back)
    for (int l = 0; l < 6; l += 2) {
        layer20(&sW[l * NHID * NHID],       &sB[l * NHID],       h,  hn,
                NEGL2E2, ONE2, ZERO2);
        layer20(&sW[(l + 1) * NHID * NHID], &sB[(l + 1) * NHID], hn, h,
                NEGL2E2, ONE2, ZERO2);
    }

    // Output layer: 20 -> 1 (dual chains, LDS.128 on W7)
    {
        const ulonglong2* w7 = reinterpret_cast<const ulonglong2*>(sW7);
        u64 accE = pack2f(sb7, sb7);
        u64 accO = ZERO2;
        #pragma unroll
        for (int k2 = 0; k2 < NHID / 2; k2++) {
            ulonglong2 w = w7[k2];
            accE = fma2(h[2 * k2],     w.x, accE);
            accO = fma2(h[2 * k2 + 1], w.y, accO);
        }
        u64 a = add2(accE, accO);
        float o0, o1;
        unpack2f(a, o0, o1);
        out[base] = o0;
        if (base + 1 < n) out[base + 1] = o1;
    }
}

extern "C" void kernel_launch(void* const* d_in, const int* in_sizes, int n_in,
                              void* d_out, int out_size)
{
    const float* t  = (const float*)d_in[0];
    const float* W0 = (const float*)d_in[1];
    const float* b0 = (const float*)d_in[2];
    const float* W1 = (const float*)d_in[3];
    const float* b1 = (const float*)d_in[4];
    const float* W2 = (const float*)d_in[5];
    const float* b2 = (const float*)d_in[6];
    const float* W3 = (const float*)d_in[7];
    const float* b3 = (const float*)d_in[8];
    const float* W4 = (const float*)d_in[9];
    const float* b4 = (const float*)d_in[10];
    const float* W5 = (const float*)d_in[11];
    const float* b5 = (const float*)d_in[12];
    const float* W6 = (const float*)d_in[13];
    const float* b6 = (const float*)d_in[14];
    const float* W7 = (const float*)d_in[15];
    const float* b7 = (const float*)d_in[16];

    const int n = in_sizes[0];
    float* out = (float*)d_out;

    const int pts_per_block = TPB * PPT;
    const int grid = (n + pts_per_block - 1) / pts_per_block;

    SpringEquationNN_kernel<<<grid, TPB>>>(
        t, W0, b0, W1, b1, W2, b2, W3, b3,
        W4, b4, W5, b5, W6, b6, W7, b7, out, n);
}

// round 7
// speedup vs baseline: 1.0529x; 1.0529x over previous
#include <cuda_runtime.h>

#define NHID 20
#define TPB  256
#define PPT  2   // points per thread = 1 f32x2 pair

typedef unsigned long long u64;

static __device__ __forceinline__ u64 pack2f(float lo, float hi) {
    u64 r;
    unsigned a = __float_as_uint(lo), b = __float_as_uint(hi);
    asm("mov.b64 %0, {%1, %2};" : "=l"(r) : "r"(a), "r"(b));
    return r;
}
static __device__ __forceinline__ void unpack2f(u64 v, float& lo, float& hi) {
    unsigned a, b;
    asm("mov.b64 {%0, %1}, %2;" : "=r"(a), "=r"(b) : "l"(v));
    lo = __uint_as_float(a);
    hi = __uint_as_float(b);
}
static __device__ __forceinline__ u64 fma2(u64 a, u64 b, u64 c) {
    u64 d;
    asm("fma.rn.f32x2 %0, %1, %2, %3;" : "=l"(d) : "l"(a), "l"(b), "l"(c));
    return d;
}
static __device__ __forceinline__ u64 mul2(u64 a, u64 b) {
    u64 d;
    asm("mul.rn.f32x2 %0, %1, %2;" : "=l"(d) : "l"(a), "l"(b));
    return d;
}
static __device__ __forceinline__ u64 add2(u64 a, u64 b) {
    u64 d;
    asm("add.rn.f32x2 %0, %1, %2;" : "=l"(d) : "l"(a), "l"(b));
    return d;
}
static __device__ __forceinline__ float ex2f(float x) {
    float r;
    asm("ex2.approx.f32 %0, %1;" : "=f"(r) : "f"(x));
    return r;
}
static __device__ __forceinline__ float rcpf(float x) {
    float r;
    asm("rcp.approx.f32 %0, %1;" : "=f"(r) : "f"(x));
    return r;
}

// silu on a packed pair: x * 1/(1+e^-x).  3 f32x2 fma-pipe ops + 4 MUFU.
static __device__ __forceinline__ u64 silu2(u64 x2, u64 negl2e2, u64 one2) {
    u64 m = mul2(x2, negl2e2);              // -x*log2(e)
    float mlo, mhi; unpack2f(m, mlo, mhi);
    u64 e = pack2f(ex2f(mlo), ex2f(mhi));   // e^-x
    u64 d = add2(e, one2);                  // 1 + e^-x
    float dlo, dhi; unpack2f(d, dlo, dhi);
    u64 r = pack2f(rcpf(dlo), rcpf(dhi));   // sigmoid
    return mul2(x2, r);
}

__global__ void __launch_bounds__(TPB, 2)   // 128 regs -> 4 warps/SMSP
SpringEquationNN_kernel(
    const float* __restrict__ t,
    const float* __restrict__ W0, const float* __restrict__ b0,
    const float* __restrict__ W1, const float* __restrict__ b1,
    const float* __restrict__ W2, const float* __restrict__ b2,
    const float* __restrict__ W3, const float* __restrict__ b3,
    const float* __restrict__ W4, const float* __restrict__ b4,
    const float* __restrict__ W5, const float* __restrict__ b5,
    const float* __restrict__ W6, const float* __restrict__ b6,
    const float* __restrict__ W7, const float* __restrict__ b7,
    float* __restrict__ out, int n)
{
    // Splat {w,w} pairs. Hidden weights TRANSPOSED: sWt[l][k*NHID + j],
    // so the k-outer inner loop reads 20 consecutive j-weights per k.
    __shared__ __align__(16) u64 sWt[6 * NHID * NHID];
    __shared__ __align__(16) u64 sB[6 * NHID];
    __shared__ __align__(16) u64 sW0[NHID], sB0[NHID], sW7[NHID], sB7[1];

    const int tid = threadIdx.x;

    for (int i = tid; i < NHID; i += TPB) {
        sW0[i] = pack2f(W0[i], W0[i]);
        sB0[i] = pack2f(b0[i], b0[i]);
        sW7[i] = pack2f(W7[i], W7[i]);
    }
    for (int i = tid; i < 6 * NHID * NHID; i += TPB) {
        int l = i / (NHID * NHID);
        int r = i - l * (NHID * NHID);
        int k = r / NHID;          // input index
        int j = r - k * NHID;      // output index
        float w;
        int src = j * NHID + k;    // row-major W[j][k]
        switch (l) {
            case 0: w = W1[src]; break;
            case 1: w = W2[src]; break;
            case 2: w = W3[src]; break;
            case 3: w = W4[src]; break;
            case 4: w = W5[src]; break;
            default: w = W6[src]; break;
        }
        sWt[i] = pack2f(w, w);
    }
    for (int i = tid; i < 6 * NHID; i += TPB) {
        int l = i / NHID;
        int r = i - l * NHID;
        float w;
        switch (l) {
            case 0: w = b1[r]; break;
            case 1: w = b2[r]; break;
            case 2: w = b3[r]; break;
            case 3: w = b4[r]; break;
            case 4: w = b5[r]; break;
            default: w = b6[r]; break;
        }
        sB[i] = pack2f(w, w);
    }
    if (tid == 0) sB7[0] = pack2f(b7[0], b7[0]);
    __syncthreads();

    const u64 NEGL2E2 = pack2f(-1.442695041f, -1.442695041f);
    const u64 ONE2    = pack2f(1.0f, 1.0f);

    const int base = (blockIdx.x * TPB + tid) * PPT;
    if (base >= n) return;

    float tx, ty;
    if (base + 2 <= n) {
        float2 v = *reinterpret_cast<const float2*>(t + base);
        tx = v.x; ty = v.y;
    } else {
        tx = t[base]; ty = 0.0f;
    }
    const u64 x0 = pack2f(tx, ty);

    u64 h[NHID];

    // Layer 0: 1 -> 20
    #pragma unroll
    for (int j = 0; j < NHID; j++)
        h[j] = silu2(fma2(x0, sW0[j], sB0[j]), NEGL2E2, ONE2);

    // Hidden layers 1..6: k-outer accumulation.
    // acc[j] is touched once per k (~30 instrs apart) -> no FMA RAW stalls;
    // each k's 10 LDS.128 have a full k of independent FMAs to hide under.
    for (int l = 0; l < 6; l++) {
        const u64* wl = &sWt[l * NHID * NHID];
        const ulonglong2* bl = reinterpret_cast<const ulonglong2*>(&sB[l * NHID]);

        u64 acc[NHID];
        #pragma unroll
        for (int j2 = 0; j2 < NHID / 2; j2++) {
            ulonglong2 bb = bl[j2];          // LDS.128 bias init
            acc[2 * j2]     = bb.x;
            acc[2 * j2 + 1] = bb.y;
        }

        #pragma unroll
        for (int k = 0; k < NHID; k++) {
            const u64 hk = h[k];
            const ulonglong2* wcol =
                reinterpret_cast<const ulonglong2*>(wl + k * NHID);
            #pragma unroll
            for (int j2 = 0; j2 < NHID / 2; j2++) {
                ulonglong2 w = wcol[j2];     // LDS.128 broadcast: 2 weights
                acc[2 * j2]     = fma2(hk, w.x, acc[2 * j2]);
                acc[2 * j2 + 1] = fma2(hk, w.y, acc[2 * j2 + 1]);
            }
        }

        // In-place: all reads of h happened above.
        #pragma unroll
        for (int j = 0; j < NHID; j++)
            h[j] = silu2(acc[j], NEGL2E2, ONE2);
    }

    // Output layer: 20 -> 1 (dual chains)
    {
        const ulonglong2* w7 = reinterpret_cast<const ulonglong2*>(sW7);
        u64 accE = sB7[0];
        u64 accO = 0ull;
        #pragma unroll
        for (int k2 = 0; k2 < NHID / 2; k2++) {
            ulonglong2 w = w7[k2];
            accE = fma2(h[2 * k2],     w.x, accE);
            accO = fma2(h[2 * k2 + 1], w.y, accO);
        }
        u64 a = add2(accE, accO);
        float o0, o1;
        unpack2f(a, o0, o1);
        if (base + 2 <= n) {
            *reinterpret_cast<float2*>(out + base) = make_float2(o0, o1);
        } else {
            out[base] = o0;
        }
    }
}

extern "C" void kernel_launch(void* const* d_in, const int* in_sizes, int n_in,
                              void* d_out, int out_size)
{
    const float* t  = (const float*)d_in[0];
    const float* W0 = (const float*)d_in[1];
    const float* b0 = (const float*)d_in[2];
    const float* W1 = (const float*)d_in[3];
    const float* b1 = (const float*)d_in[4];
    const float* W2 = (const float*)d_in[5];
    const float* b2 = (const float*)d_in[6];
    const float* W3 = (const float*)d_in[7];
    const float* b3 = (const float*)d_in[8];
    const float* W4 = (const float*)d_in[9];
    const float* b4 = (const float*)d_in[10];
    const float* W5 = (const float*)d_in[11];
    const float* b5 = (const float*)d_in[12];
    const float* W6 = (const float*)d_in[13];
    const float* b6 = (const float*)d_in[14];
    const float* W7 = (const float*)d_in[15];
    const float* b7 = (const float*)d_in[16];

    const int n = in_sizes[0];
    float* out = (float*)d_out;

    const int pts_per_block = TPB * PPT;
    const int grid = (n + pts_per_block - 1) / pts_per_block;

    SpringEquationNN_kernel<<<grid, TPB>>>(
        t, W0, b0, W1, b1, W2, b2, W3, b3,
        W4, b4, W5, b5, W6, b6, W7, b7, out, n);
}

// round 10
// speedup vs baseline: 1.0917x; 1.0369x over previous
#include <cuda_runtime.h>

#define NHID 20
#define TPB  256
#define PPT  2
#define NWH  (6 * NHID * NHID)

typedef unsigned long long u64;

struct CParams {
    u64 Wt[NWH];        // hidden weights, transposed splats: [l][k*NHID + j]
    u64 B[6 * NHID];    // hidden biases, splats
    u64 W0[NHID];
    u64 B0[NHID];
    u64 W7[NHID];
    u64 B7;
};

__constant__ CParams cP;
__device__   CParams gStage;

static __device__ __forceinline__ u64 pack2f(float lo, float hi) {
    u64 r;
    unsigned a = __float_as_uint(lo), b = __float_as_uint(hi);
    asm("mov.b64 %0, {%1, %2};" : "=l"(r) : "r"(a), "r"(b));
    return r;
}
static __device__ __forceinline__ void unpack2f(u64 v, float& lo, float& hi) {
    unsigned a, b;
    asm("mov.b64 {%0, %1}, %2;" : "=r"(a), "=r"(b) : "l"(v));
    lo = __uint_as_float(a);
    hi = __uint_as_float(b);
}
static __device__ __forceinline__ u64 fma2(u64 a, u64 b, u64 c) {
    u64 d;
    asm("fma.rn.f32x2 %0, %1, %2, %3;" : "=l"(d) : "l"(a), "l"(b), "l"(c));
    return d;
}
static __device__ __forceinline__ u64 mul2(u64 a, u64 b) {
    u64 d;
    asm("mul.rn.f32x2 %0, %1, %2;" : "=l"(d) : "l"(a), "l"(b));
    return d;
}
static __device__ __forceinline__ u64 add2(u64 a, u64 b) {
    u64 d;
    asm("add.rn.f32x2 %0, %1, %2;" : "=l"(d) : "l"(a), "l"(b));
    return d;
}
static __device__ __forceinline__ float ex2f(float x) {
    float r;
    asm("ex2.approx.f32 %0, %1;" : "=f"(r) : "f"(x));
    return r;
}
static __device__ __forceinline__ float rcpf(float x) {
    float r;
    asm("rcp.approx.f32 %0, %1;" : "=f"(r) : "f"(x));
    return r;
}

// silu on a packed pair: x * 1/(1+e^-x).  3 f32x2 fma-pipe ops + 4 MUFU.
static __device__ __forceinline__ u64 silu2(u64 x2, u64 negl2e2, u64 one2) {
    u64 m = mul2(x2, negl2e2);
    float mlo, mhi; unpack2f(m, mlo, mhi);
    u64 e = pack2f(ex2f(mlo), ex2f(mhi));
    u64 d = add2(e, one2);
    float dlo, dhi; unpack2f(d, dlo, dhi);
    u64 r = pack2f(rcpf(dlo), rcpf(dhi));
    return mul2(x2, r);
}

// Prep: build transposed splat-pair weight tables in gStage (then memcpy'd
// into the __constant__ aperture; const cache is flushed at launch).
__global__ void prep_kernel(
    const float* __restrict__ W0, const float* __restrict__ b0,
    const float* __restrict__ W1, const float* __restrict__ b1,
    const float* __restrict__ W2, const float* __restrict__ b2,
    const float* __restrict__ W3, const float* __restrict__ b3,
    const float* __restrict__ W4, const float* __restrict__ b4,
    const float* __restrict__ W5, const float* __restrict__ b5,
    const float* __restrict__ W6, const float* __restrict__ b6,
    const float* __restrict__ W7, const float* __restrict__ b7)
{
    const int tid = blockIdx.x * blockDim.x + threadIdx.x;
    const int nthr = gridDim.x * blockDim.x;

    for (int i = tid; i < NWH; i += nthr) {
        int l = i / (NHID * NHID);
        int r = i - l * (NHID * NHID);
        int k = r / NHID;
        int j = r - k * NHID;
        int src = j * NHID + k;   // row-major W[j][k]
        float w;
        switch (l) {
            case 0: w = W1[src]; break;
            case 1: w = W2[src]; break;
            case 2: w = W3[src]; break;
            case 3: w = W4[src]; break;
            case 4: w = W5[src]; break;
            default: w = W6[src]; break;
        }
        gStage.Wt[i] = pack2f(w, w);
    }
    for (int i = tid; i < 6 * NHID; i += nthr) {
        int l = i / NHID;
        int r = i - l * NHID;
        float w;
        switch (l) {
            case 0: w = b1[r]; break;
            case 1: w = b2[r]; break;
            case 2: w = b3[r]; break;
            case 3: w = b4[r]; break;
            case 4: w = b5[r]; break;
            default: w = b6[r]; break;
        }
        gStage.B[i] = pack2f(w, w);
    }
    for (int i = tid; i < NHID; i += nthr) {
        gStage.W0[i] = pack2f(W0[i], W0[i]);
        gStage.B0[i] = pack2f(b0[i], b0[i]);
        gStage.W7[i] = pack2f(W7[i], W7[i]);
    }
    if (tid == 0) gStage.B7 = pack2f(b7[0], b7[0]);
}

__global__ void __launch_bounds__(TPB, 2)
SpringEquationNN_kernel(const float* __restrict__ t,
                        float* __restrict__ out, int n)
{
    const u64 NEGL2E2 = pack2f(-1.442695041f, -1.442695041f);
    const u64 ONE2    = pack2f(1.0f, 1.0f);

    const int base = (blockIdx.x * TPB + threadIdx.x) * PPT;
    if (base >= n) return;

    float tx, ty;
    if (base + 2 <= n) {
        float2 v = *reinterpret_cast<const float2*>(t + base);
        tx = v.x; ty = v.y;
    } else {
        tx = t[base]; ty = 0.0f;
    }
    const u64 x0 = pack2f(tx, ty);

    u64 h[NHID];

    // Layer 0: 1 -> 20 (immediate const offsets)
    #pragma unroll
    for (int j = 0; j < NHID; j++)
        h[j] = silu2(fma2(x0, cP.W0[j], cP.B0[j]), NEGL2E2, ONE2);

    // Hidden layers 1..6: k-outer register accumulation; weights from the
    // constant port (uniform base + immediate offsets), no smem, no addr ALU.
    for (int l = 0; l < 6; l++) {
        const ulonglong2* w2 =
            reinterpret_cast<const ulonglong2*>(cP.Wt + l * NHID * NHID);
        const ulonglong2* b2v =
            reinterpret_cast<const ulonglong2*>(cP.B + l * NHID);

        u64 acc[NHID];
        #pragma unroll
        for (int j2 = 0; j2 < NHID / 2; j2++) {
            ulonglong2 bb = b2v[j2];
            acc[2 * j2]     = bb.x;
            acc[2 * j2 + 1] = bb.y;
        }

        #pragma unroll
        for (int k = 0; k < NHID; k++) {
            const u64 hk = h[k];
            #pragma unroll
            for (int j2 = 0; j2 < NHID / 2; j2++) {
                ulonglong2 w = w2[k * (NHID / 2) + j2];  // const .128 load
                acc[2 * j2]     = fma2(hk, w.x, acc[2 * j2]);
                acc[2 * j2 + 1] = fma2(hk, w.y, acc[2 * j2 + 1]);
            }
        }

        #pragma unroll
        for (int j = 0; j < NHID; j++)
            h[j] = silu2(acc[j], NEGL2E2, ONE2);
    }

    // Output layer: 20 -> 1 (dual chains)
    {
        const ulonglong2* w7 = reinterpret_cast<const ulonglong2*>(cP.W7);
        u64 accE = cP.B7;
        u64 accO = 0ull;
        #pragma unroll
        for (int k2 = 0; k2 < NHID / 2; k2++) {
            ulonglong2 w = w7[k2];
            accE = fma2(h[2 * k2],     w.x, accE);
            accO = fma2(h[2 * k2 + 1], w.y, accO);
        }
        u64 a = add2(accE, accO);
        float o0, o1;
        unpack2f(a, o0, o1);
        if (base + 2 <= n) {
            *reinterpret_cast<float2*>(out + base) = make_float2(o0, o1);
        } else {
            out[base] = o0;
        }
    }
}

extern "C" void kernel_launch(void* const* d_in, const int* in_sizes, int n_in,
                              void* d_out, int out_size)
{
    const float* t  = (const float*)d_in[0];
    const float* W0 = (const float*)d_in[1];
    const float* b0 = (const float*)d_in[2];
    const float* W1 = (const float*)d_in[3];
    const float* b1 = (const float*)d_in[4];
    const float* W2 = (const float*)d_in[5];
    const float* b2 = (const float*)d_in[6];
    const float* W3 = (const float*)d_in[7];
    const float* b3 = (const float*)d_in[8];
    const float* W4 = (const float*)d_in[9];
    const float* b4 = (const float*)d_in[10];
    const float* W5 = (const float*)d_in[11];
    const float* b5 = (const float*)d_in[12];
    const float* W6 = (const float*)d_in[13];
    const float* b6 = (const float*)d_in[14];
    const float* W7 = (const float*)d_in[15];
    const float* b7 = (const float*)d_in[16];

    const int n = in_sizes[0];
    float* out = (float*)d_out;

    // 1) Build splat tables in device-global staging.
    prep_kernel<<<4, 256>>>(W0, b0, W1, b1, W2, b2, W3, b3,
                            W4, b4, W5, b5, W6, b6, W7, b7);

    // 2) Stage -> constant aperture (D2D async memcpy: graph-capturable).
    void* cAddr = nullptr;
    void* gAddr = nullptr;
    cudaGetSymbolAddress(&cAddr, cP);
    cudaGetSymbolAddress(&gAddr, gStage);
    cudaMemcpyAsync(cAddr, gAddr, sizeof(CParams), cudaMemcpyDeviceToDevice);

    // 3) Main evaluation.
    const int pts_per_block = TPB * PPT;
    const int grid = (n + pts_per_block - 1) / pts_per_block;
    SpringEquationNN_kernel<<<grid, TPB>>>(t, out, n);
}